// round 11
// baseline (speedup 1.0000x reference)
#include <cuda_runtime.h>
#include <math_constants.h>

#define B_    4
#define C_    256
#define H_    64
#define W_    64
#define NROI  128
#define PLANE 4096            // 64*64 floats, stride 64 (row-major access only)

// Block = (b, channel-pair): stages both planes; warp-task = (roi, ch-pair).
// Phase A: warp-uniform column-max per row-stripe (lanes = aligned float2 over
// roi x-extent). Phase B: 49 bins reduce <=7 colmax entries each.
// Bin bounds: exact integer math, bit-identical to reference f32 bounds
// (rel_err == 0 in rounds 4-10). Deterministic ballot compaction from R10.
__global__ __launch_bounds__(256) void roi_pool_sep(
    const float* __restrict__ feat,
    const int*   __restrict__ rois,
    float*       __restrict__ out)
{
    __shared__ __align__(16) float plane[2 * PLANE];        // 32 KB
    __shared__ __align__(16) float cmax[8][2][7][52];       // per-warp colmax scratch
    __shared__ int s_idx[NROI], s_x1[NROI], s_y1[NROI], s_nl[NROI];
    __shared__ unsigned char s_hb[NROI][8], s_wb[NROI][8];
    __shared__ int s_wcnt[4];

    const int tid  = threadIdx.x;
    const int lane = tid & 31;
    const int wid  = tid >> 5;
    const int blk  = blockIdx.x;          // b*128 + cpair
    const int b    = blk >> 7;
    const int c0   = (blk & 127) << 1;    // channels c0, c0+1

    // ---- phase 0: deterministic compaction (order = original roi index) ----
    bool match = false;
    if (tid < NROI)
        match = (__ldg(rois + tid * 5) == b);
    const unsigned mball = __ballot_sync(0xffffffffu, match);
    if (lane == 0 && wid < 4) s_wcnt[wid] = __popc(mball);
    __syncthreads();
    const int cnt = s_wcnt[0] + s_wcnt[1] + s_wcnt[2] + s_wcnt[3];

    if (match) {
        int p = __popc(mball & ((1u << lane) - 1u));
        for (int w = 0; w < wid; ++w) p += s_wcnt[w];
        const int x1 = __ldg(rois + tid * 5 + 1);
        const int y1 = __ldg(rois + tid * 5 + 2);
        const int x2 = __ldg(rois + tid * 5 + 3);
        const int y2 = __ldg(rois + tid * 5 + 4);
        const int rh = y2 - y1 + 1;       // 5..48
        const int rw = x2 - x1 + 1;       // 5..48
        s_idx[p] = tid;
        s_x1[p]  = x1;
        s_y1[p]  = y1;
        s_nl[p]  = ((x2 - (x1 & ~1)) >> 1) + 1;   // float2 lanes needed (<=25)
        #pragma unroll
        for (int i = 0; i < 8; ++i) {
            s_hb[p][i] = (unsigned char)((i * rh) / 7);
            s_wb[p][i] = (unsigned char)((i * rw) / 7);
        }
    }

    // ---- phase 1: stage the two planes (2048 float4, 8 per thread) ----
    const float4* src = (const float4*)(feat + ((size_t)b * C_ + c0) * PLANE);
    float4* dst = (float4*)plane;
    #pragma unroll
    for (int kk = 0; kk < 8; ++kk)
        dst[kk * 256 + tid] = __ldg(src + kk * 256 + tid);
    __syncthreads();

    // ---- phase 2: warp-tasks k = wid, wid+8, ... ----
    for (int k = wid; k < cnt; k += 8) {
        const int x1 = s_x1[k], y1 = s_y1[k], nl = s_nl[k];
        const int xb = x1 & ~1;           // even-aligned start column
        const bool act = lane < nl;

        // -- Phase A: column maxima per row-stripe (warp-uniform bounds) --
        if (act) {
            const float* p0 = plane + y1 * W_ + xb + 2 * lane;
            #pragma unroll
            for (int i = 0; i < 7; ++i) {
                const int hs = s_hb[k][i], he = s_hb[k][i + 1];
                float2 a = make_float2(-CUDART_INF_F, -CUDART_INF_F);
                float2 c = a;
                const float* q = p0 + hs * W_;
                for (int y = hs; y < he; ++y) {
                    const float2 v0 = *(const float2*)q;
                    const float2 v1 = *(const float2*)(q + PLANE);
                    a.x = fmaxf(a.x, v0.x);  a.y = fmaxf(a.y, v0.y);
                    c.x = fmaxf(c.x, v1.x);  c.y = fmaxf(c.y, v1.y);
                    q += W_;
                }
                *(float2*)&cmax[wid][0][i][2 * lane] = a;
                *(float2*)&cmax[wid][1][i][2 * lane] = c;
            }
        }
        __syncwarp();

        // -- Phase B: 49 bins, each max over <=7 colmax entries --
        const int ox = x1 & 1;            // roi-relative col rx lives at index rx+ox
        const size_t ob = ((size_t)s_idx[k] * C_ + c0) * 49;
        #pragma unroll
        for (int r = 0; r < 2; ++r) {
            const int bin = lane + r * 32;
            if (bin < 49) {
                const int i = (bin * 9363) >> 16;    // bin / 7 for bin < 49
                const int j = bin - i * 7;
                const int hs = s_hb[k][i], he = s_hb[k][i + 1];
                const int ws = s_wb[k][j], we = s_wb[k][j + 1];
                const bool valid = (he > hs) && (we > ws);

                float m0 = -CUDART_INF_F, m1 = -CUDART_INF_F;
                for (int rx = ws; rx < we; ++rx) {
                    m0 = fmaxf(m0, cmax[wid][0][i][rx + ox]);
                    m1 = fmaxf(m1, cmax[wid][1][i][rx + ox]);
                }
                out[ob + bin]      = valid ? m0 : 0.0f;
                out[ob + 49 + bin] = valid ? m1 : 0.0f;
            }
        }
        __syncwarp();   // cmax[wid] is reused by the next task
    }
}

extern "C" void kernel_launch(void* const* d_in, const int* in_sizes, int n_in,
                              void* d_out, int out_size) {
    const float* features = (const float*)d_in[0];
    const int*   rois     = (const int*)d_in[1];
    float*       out      = (float*)d_out;

    roi_pool_sep<<<B_ * (C_ / 2), 256>>>(features, rois, out);
}